// round 16
// baseline (speedup 1.0000x reference)
#include <cuda_runtime.h>
#include <math.h>

#define H    5120
#define NH   128
#define QLR  1536
#define DR   64
#define KVLR 512
#define DV   128
#define DN   128
#define DQ   192
#define BMAX 2
#define KVMAX 2048

#define NSM     148
#define PBLOCKS (NSM * 12)        // persistent grid for oproj: 12 x 128 thr / SM
#define PWARPS  (PBLOCKS * 4)

// ---------------- scratch (device globals; no allocation allowed) ----------------
__device__ float g_qa[BMAX * QLR];
__device__ float g_q[BMAX * NH * DQ];
__device__ float g_qpe[BMAX * NH * DR];
__device__ float g_qabs[BMAX * NH * KVLR];
__device__ float g_kpe[BMAX * KVMAX * DR];
__device__ float g_scores[BMAX * NH * KVMAX];
__device__ float g_part[4][BMAX * NH * KVLR];
__device__ float g_outv[BMAX * NH * DV];
__device__ float g_opart0[H * 16];
__device__ float g_opart1[H * 16];

__device__ __forceinline__ float warp_sum(float v) {
    #pragma unroll
    for (int o = 16; o; o >>= 1) v += __shfl_xor_sync(0xFFFFFFFFu, v, o);
    return v;
}

// ---- packed fp32x2 helpers (sm_100+; SASS FFMA2 -> 2x fp32 MAC rate, bit-exact) ----
__device__ __forceinline__ unsigned long long pack2(float lo, float hi) {
    unsigned long long r;
    asm("mov.b64 %0, {%1, %2};" : "=l"(r) : "f"(lo), "f"(hi));
    return r;
}
__device__ __forceinline__ void unpack2(unsigned long long v, float& lo, float& hi) {
    asm("mov.b64 {%0, %1}, %2;" : "=f"(lo), "=f"(hi) : "l"(v));
}
__device__ __forceinline__ void ffma2(unsigned long long& d, unsigned long long a, unsigned long long b) {
    asm("fma.rn.f32x2 %0, %1, %2, %0;" : "+l"(d) : "l"(a), "l"(b));
}

// ---------------- RoPE on k_pe cache (launched 5th; independent) ----------------
#define LOG2_THETA 13.287712379549449f
__global__ void __launch_bounds__(256) rope_k_kernel(const float* __restrict__ kpe, int KV) {
    int idx = blockIdx.x * 256 + threadIdx.x;
    if (idx >= 2 * KV * 32) return;
    int i = idx & 31;
    int k = (idx >> 5) % KV;
    int b = idx / (KV * 32);
    float ifr = exp2f(-LOG2_THETA * (float)(2 * i) / 64.0f);
    float s, c; __sincosf((float)k * ifr, &s, &c);
    size_t base = ((size_t)b * KV + k) * DR + 2 * i;
    float x0 = kpe[base], x1 = kpe[base + 1];
    g_kpe[base]     = x0 * c - x1 * s;
    g_kpe[base + 1] = x0 * s + x1 * c;
}

// ---------------- q_a = hidden @ q_a_w^T (block per row) ----------------
__global__ void __launch_bounds__(128) qa_gemv(const float* __restrict__ hs, const float* __restrict__ w) {
    int row = blockIdx.x;
    int tid = threadIdx.x;  // 128
    const float4* wr = (const float4*)(w + (size_t)row * H);
    const float4* x0 = (const float4*)hs;
    const float4* x1 = (const float4*)(hs + H);
    float a0 = 0.f, a1 = 0.f;
    #pragma unroll 10
    for (int c = tid; c < H / 4; c += 128) {
        float4 wv = __ldcs(&wr[c]);
        float4 v0 = x0[c], v1 = x1[c];
        a0 += wv.x * v0.x + wv.y * v0.y + wv.z * v0.z + wv.w * v0.w;
        a1 += wv.x * v1.x + wv.y * v1.y + wv.z * v1.z + wv.w * v1.w;
    }
    a0 = warp_sum(a0); a1 = warp_sum(a1);
    __shared__ float r0[4], r1[4];
    int lane = tid & 31, wid = tid >> 5;
    if (!lane) { r0[wid] = a0; r1[wid] = a1; }
    __syncthreads();
    if (tid == 0) g_qa[row]       = r0[0] + r0[1] + r0[2] + r0[3];
    if (tid == 1) g_qa[QLR + row] = r1[0] + r1[1] + r1[2] + r1[3];
}

// ---------------- RMSNorm(q_a) in place ----------------
__global__ void __launch_bounds__(512) rmsnorm_k(const float* __restrict__ lnw) {
    int b = blockIdx.x, tid = threadIdx.x;
    float x[3]; float ss = 0.f;
    #pragma unroll
    for (int i = 0; i < 3; i++) { x[i] = g_qa[b * QLR + tid + i * 512]; ss += x[i] * x[i]; }
    __shared__ float red[512];
    red[tid] = ss; __syncthreads();
    for (int s = 256; s; s >>= 1) { if (tid < s) red[tid] += red[tid + s]; __syncthreads(); }
    float inv = rsqrtf(red[0] / (float)QLR + 1e-6f);
    #pragma unroll
    for (int i = 0; i < 3; i++)
        g_qa[b * QLR + tid + i * 512] = x[i] * inv * lnw[tid + i * 512];
}

// ---------------- q = q_a @ q_b_w^T (R6-best: 2 rows/warp, grid 3072x128) ----------------
__global__ void __launch_bounds__(128) qb_gemv(const float* __restrict__ w) {
    int wid  = threadIdx.x >> 5;
    int lane = threadIdx.x & 31;
    int r0 = blockIdx.x * 8 + wid * 2;           // rows r0, r0+1
    const float4* w0 = (const float4*)(w + (size_t)r0 * QLR);
    const float4* w1 = (const float4*)(w + (size_t)(r0 + 1) * QLR);
    const float4* x0 = (const float4*)g_qa;
    const float4* x1 = (const float4*)(g_qa + QLR);
    float a00 = 0.f, a01 = 0.f, a10 = 0.f, a11 = 0.f;
    #pragma unroll 6
    for (int c = lane; c < QLR / 4; c += 32) {
        float4 wa = __ldcs(&w0[c]);
        float4 wb = __ldcs(&w1[c]);
        float4 v0 = x0[c], v1 = x1[c];
        a00 += wa.x * v0.x + wa.y * v0.y + wa.z * v0.z + wa.w * v0.w;
        a01 += wa.x * v1.x + wa.y * v1.y + wa.z * v1.z + wa.w * v1.w;
        a10 += wb.x * v0.x + wb.y * v0.y + wb.z * v0.z + wb.w * v0.w;
        a11 += wb.x * v1.x + wb.y * v1.y + wb.z * v1.z + wb.w * v1.w;
    }
    a00 = warp_sum(a00); a01 = warp_sum(a01);
    a10 = warp_sum(a10); a11 = warp_sum(a11);
    if (!lane) {
        g_q[r0] = a00;           g_q[NH * DQ + r0] = a01;
        g_q[r0 + 1] = a10;       g_q[NH * DQ + r0 + 1] = a11;
    }
}

// ------- q_abs + fused rope_q.  grid 256 = (head, c-half), 256 thr.  -- ncu slot -------
__global__ void __launch_bounds__(256) qabs_kernel(const float* __restrict__ kvb, int KV) {
    int h = blockIdx.x >> 1, half = blockIdx.x & 1;
    int tid = threadIdx.x;     // 256
    __shared__ float qn[2][DN];
    // all 256 threads: tid -> (b = tid>>7, d = tid&127)
    qn[tid >> 7][tid & 127] = g_q[(tid >> 7) * NH * DQ + h * DQ + (tid & 127)];
    // fused rope_q handled once per head (by the half==1 block), threads 0..63
    if (half == 1 && tid < 64) {
        int b = tid >> 5, i = tid & 31;
        float ifr = exp2f(-LOG2_THETA * (float)(2 * i) / 64.0f);
        float s, co; __sincosf((float)(KV - 1) * ifr, &s, &co);
        float x0 = g_q[b * NH * DQ + h * DQ + DN + 2 * i];
        float x1 = g_q[b * NH * DQ + h * DQ + DN + 2 * i + 1];
        g_qpe[(b * NH + h) * DR + 2 * i]     = x0 * co - x1 * s;
        g_qpe[(b * NH + h) * DR + 2 * i + 1] = x0 * s + x1 * co;
    }
    __syncthreads();
    int c = half * 256 + tid;
    const float* wp = kvb + (size_t)(h * 256) * KVLR + c;
    float a0 = 0.f, a1 = 0.f;
    #pragma unroll 16
    for (int d = 0; d < DN; d++) {
        float w = __ldcs(&wp[(size_t)d * KVLR]);
        a0 += qn[0][d] * w;
        a1 += qn[1][d] * w;
    }
    g_qabs[h * KVLR + c] = a0;
    g_qabs[NH * KVLR + h * KVLR + c] = a1;
}

// ---------------- scores: 32-head x 128-k tiles, grid (KV/128, 4, B) ----------------
__global__ void __launch_bounds__(256) scores_kernel(const float* __restrict__ ckv, int KV) {
    __shared__ float Qs[32][66];
    __shared__ float KsT[64][130];
    int b = blockIdx.z, h0 = blockIdx.y * 32, k0 = blockIdx.x * 128;
    int tid = threadIdx.x, lane = tid & 31, wid = tid >> 5;
    unsigned long long acc[4][2] = {};
    for (int chunk = 0; chunk < 9; chunk++) {
        if (chunk < 8) {
            int c0 = chunk * 64;
            #pragma unroll
            for (int t = tid; t < 32 * 16; t += 256) {
                int r = t >> 4, c4 = t & 15;
                float4 v = *(const float4*)&g_qabs[((b * NH) + h0 + r) * KVLR + c0 + c4 * 4];
                Qs[r][c4*4+0] = v.x; Qs[r][c4*4+1] = v.y; Qs[r][c4*4+2] = v.z; Qs[r][c4*4+3] = v.w;
            }
            int c = tid & 63, kk = tid >> 6;
            #pragma unroll 8
            for (int kq = 0; kq < 32; kq++) {
                int k = kq * 4 + kk;
                KsT[c][k] = ckv[((size_t)b * KV + k0 + k) * KVLR + c0 + c];
            }
        } else {
            #pragma unroll
            for (int t = tid; t < 32 * 16; t += 256) {
                int r = t >> 4, c4 = t & 15;
                float4 v = *(const float4*)&g_qpe[((b * NH) + h0 + r) * DR + c4 * 4];
                Qs[r][c4*4+0] = v.x; Qs[r][c4*4+1] = v.y; Qs[r][c4*4+2] = v.z; Qs[r][c4*4+3] = v.w;
            }
            int c = tid & 63, kk = tid >> 6;
            #pragma unroll 8
            for (int kq = 0; kq < 32; kq++) {
                int k = kq * 4 + kk;
                KsT[c][k] = g_kpe[((size_t)b * KV + k0 + k) * DR + c];
            }
        }
        __syncthreads();
        #pragma unroll 8
        for (int cc = 0; cc < 64; cc++) {
            unsigned long long kA = *(const unsigned long long*)&KsT[cc][lane * 2];
            unsigned long long kB = *(const unsigned long long*)&KsT[cc][lane * 2 + 64];
            #pragma unroll
            for (int i = 0; i < 4; i++) {
                float q = Qs[wid + 8 * i][cc];
                unsigned long long qq = pack2(q, q);
                ffma2(acc[i][0], qq, kA);
                ffma2(acc[i][1], qq, kB);
            }
        }
        __syncthreads();
    }
    const float sc = rsqrtf((float)DQ);
    #pragma unroll
    for (int i = 0; i < 4; i++) {
        #pragma unroll
        for (int jj = 0; jj < 2; jj++) {
            float lo, hi; unpack2(acc[i][jj], lo, hi);
            float2 v = make_float2(lo * sc, hi * sc);
            *(float2*)&g_scores[(size_t)(b * NH + h0 + wid + 8 * i) * KV + k0 + lane * 2 + 64 * jj] = v;
        }
    }
}

// ---------------- softmax over k ----------------
__global__ void __launch_bounds__(256) softmax_kernel(int KV) {
    int bh = blockIdx.x;
    float* s = g_scores + (size_t)bh * KV;
    int tid = threadIdx.x;
    int n = KV >> 8;
    float v[8];
    float m = -1e30f;
    for (int i = 0; i < n; i++) { v[i] = s[tid + i * 256]; m = fmaxf(m, v[i]); }
    __shared__ float red[256];
    red[tid] = m; __syncthreads();
    for (int st = 128; st; st >>= 1) { if (tid < st) red[tid] = fmaxf(red[tid], red[tid + st]); __syncthreads(); }
    m = red[0]; __syncthreads();
    float sum = 0.f;
    for (int i = 0; i < n; i++) { v[i] = __expf(v[i] - m); sum += v[i]; }
    red[tid] = sum; __syncthreads();
    for (int st = 128; st; st >>= 1) { if (tid < st) red[tid] += red[tid + st]; __syncthreads(); }
    float inv = 1.f / red[0];
    for (int i = 0; i < n; i++) s[tid + i * 256] = v[i] * inv;
}

// ---------------- partial attn·c_kv (split-K = 4), FFMA2-packed ----------------
__global__ void __launch_bounds__(256) actv_kernel(const float* __restrict__ ckv, int KV) {
    __shared__ float As[32][68];
    __shared__ float Bs[64][128];
    int c0 = blockIdx.x * 128, h0 = blockIdx.y * 32;
    int b = blockIdx.z >> 2, sp = blockIdx.z & 3;
    int kbeg = sp * (KV / 4);
    int tid = threadIdx.x, lane = tid & 31, wid = tid >> 5;
    unsigned long long acc[4][2] = {};
    for (int kc0 = kbeg; kc0 < kbeg + KV / 4; kc0 += 64) {
        #pragma unroll
        for (int t = tid; t < 32 * 16; t += 256) {
            int r = t >> 4, c4 = t & 15;
            float4 v = *(const float4*)&g_scores[(size_t)(b * NH + h0 + r) * KV + kc0 + c4 * 4];
            *(float4*)&As[r][c4 * 4] = v;
        }
        #pragma unroll
        for (int t = tid; t < 64 * 32; t += 256) {
            int r = t >> 5, c4 = t & 31;
            *(float4*)&Bs[r][c4 * 4] =
                *(const float4*)&ckv[((size_t)b * KV + kc0 + r) * KVLR + c0 + c4 * 4];
        }
        __syncthreads();
        #pragma unroll 8
        for (int kc = 0; kc < 64; kc++) {
            unsigned long long b0 = *(const unsigned long long*)&Bs[kc][lane * 4];
            unsigned long long b1 = *(const unsigned long long*)&Bs[kc][lane * 4 + 2];
            #pragma unroll
            for (int i = 0; i < 4; i++) {
                float a = As[wid + 8 * i][kc];
                unsigned long long aa = pack2(a, a);
                ffma2(acc[i][0], aa, b0);
                ffma2(acc[i][1], aa, b1);
            }
        }
        __syncthreads();
    }
    #pragma unroll
    for (int i = 0; i < 4; i++) {
        float x0, x1, x2, x3;
        unpack2(acc[i][0], x0, x1);
        unpack2(acc[i][1], x2, x3);
        float4 v = make_float4(x0, x1, x2, x3);
        *(float4*)&g_part[sp][(size_t)(b * NH + h0 + wid + 8 * i) * KVLR + c0 + lane * 4] = v;
    }
}

// ---------------- out_v: grid 1024 = (h, dv-eighth), warp = 2 dv rows ----------------
__global__ void __launch_bounds__(256) outv_kernel(const float* __restrict__ kvb) {
    int h = blockIdx.x >> 3, dvE = blockIdx.x & 7;
    __shared__ float as[2][KVLR];
    int tid = threadIdx.x;
    for (int t = tid; t < 2 * KVLR; t += 256) {
        int b = t >> 9, c = t & 511;
        float v = 0.f;
        #pragma unroll
        for (int sp = 0; sp < 4; sp++) v += g_part[sp][(size_t)(b * NH + h) * KVLR + c];
        as[b][c] = v;
    }
    __syncthreads();
    int lane = tid & 31, wid = tid >> 5;
    int dv0 = dvE * 16 + wid * 2;
    const float4* wp0 = (const float4*)(kvb + (size_t)(h * 256 + 128 + dv0 + 0) * KVLR);
    const float4* wp1 = (const float4*)(kvb + (size_t)(h * 256 + 128 + dv0 + 1) * KVLR);
    float a0[2] = {0.f, 0.f};
    float a1[2] = {0.f, 0.f};
    #pragma unroll
    for (int c4 = lane; c4 < KVLR / 4; c4 += 32) {
        float4 w0 = __ldcs(&wp0[c4]);
        float4 w1 = __ldcs(&wp1[c4]);
        float4 v0 = *(const float4*)&as[0][c4 * 4];
        float4 v1 = *(const float4*)&as[1][c4 * 4];
        a0[0] += w0.x*v0.x + w0.y*v0.y + w0.z*v0.z + w0.w*v0.w;
        a1[0] += w0.x*v1.x + w0.y*v1.y + w0.z*v1.z + w0.w*v1.w;
        a0[1] += w1.x*v0.x + w1.y*v0.y + w1.z*v0.z + w1.w*v0.w;
        a1[1] += w1.x*v1.x + w1.y*v1.y + w1.z*v1.z + w1.w*v1.w;
    }
    #pragma unroll
    for (int r = 0; r < 2; r++) {
        a0[r] = warp_sum(a0[r]);
        a1[r] = warp_sum(a1[r]);
    }
    if (!lane) {
        #pragma unroll
        for (int r = 0; r < 2; r++) {
            g_outv[h * DV + dv0 + r] = a0[r];
            g_outv[NH * DV + h * DV + dv0 + r] = a1[r];
        }
    }
}

// ------- o_proj stage 1: persistent warp-tasks (row, sixteenth of K) -------
__global__ void __launch_bounds__(128, 12) oproj_part(const float* __restrict__ ow) {
    int lane = threadIdx.x & 31;
    int wgid = (blockIdx.x * 4) + (threadIdx.x >> 5);
    const int NT = H * 16;
    const float4* x0 = (const float4*)g_outv;
    const float4* x1 = (const float4*)(g_outv + NH * DV);
    for (int t = wgid; t < NT; t += PWARPS) {
        int row = t >> 4, six = t & 15;
        int cbase = six * 256;
        const float4* wr = (const float4*)(ow + (size_t)row * (NH * DV)) + cbase;
        const float4* p0 = x0 + cbase;
        const float4* p1 = x1 + cbase;
        float a0 = 0.f, a1 = 0.f;
        #pragma unroll
        for (int c = lane; c < 256; c += 32) {
            float4 wv = __ldcs(&wr[c]);
            float4 v0 = p0[c], v1 = p1[c];
            a0 += wv.x * v0.x + wv.y * v0.y + wv.z * v0.z + wv.w * v0.w;
            a1 += wv.x * v1.x + wv.y * v1.y + wv.z * v1.z + wv.w * v1.w;
        }
        a0 = warp_sum(a0); a1 = warp_sum(a1);
        if (!lane) { g_opart0[t] = a0; g_opart1[t] = a1; }
    }
}

// ------- o_proj stage 2: combine 16 partials per output -------
__global__ void __launch_bounds__(128) oproj_combine(float* __restrict__ out) {
    int idx = blockIdx.x * 128 + threadIdx.x;
    if (idx >= 2 * H) return;
    int b = idx >= H;
    int row = b ? (idx - H) : idx;
    const float4* p = (const float4*)((b ? g_opart1 : g_opart0) + row * 16);
    float s = 0.f;
    #pragma unroll
    for (int q = 0; q < 4; q++) {
        float4 v = p[q];
        s += v.x + v.y + v.z + v.w;
    }
    out[idx] = s;
}

// ---------------- launch ----------------
extern "C" void kernel_launch(void* const* d_in, const int* in_sizes, int n_in,
                              void* d_out, int out_size) {
    const float* hidden = (const float*)d_in[0];
    const float* ckv    = (const float*)d_in[1];
    const float* kpe    = (const float*)d_in[2];
    const float* qaw    = (const float*)d_in[3];
    const float* lnw    = (const float*)d_in[4];
    const float* qbw    = (const float*)d_in[5];
    const float* kvb    = (const float*)d_in[6];
    const float* ow     = (const float*)d_in[7];
    float* out = (float*)d_out;

    int B  = in_sizes[0] / H;          // 2
    int KV = in_sizes[2] / (B * DR);   // 2048

    qa_gemv<<<QLR, 128>>>(hidden, qaw);                           // 1
    rmsnorm_k<<<B, 512>>>(lnw);                                   // 2
    qb_gemv<<<(NH * DQ) / 8, 128>>>(qbw);                         // 3
    qabs_kernel<<<NH * 2, 256>>>(kvb, KV);                        // 4  <- ncu slot
    rope_k_kernel<<<(B * KV * 32 + 255) / 256, 256>>>(kpe, KV);   // 5 (indep; done before scores)
    scores_kernel<<<dim3(KV / 128, NH / 32, B), 256>>>(ckv, KV);  // 6
    softmax_kernel<<<B * NH, 256>>>(KV);                          // 7
    actv_kernel<<<dim3(KVLR / 128, NH / 32, B * 4), 256>>>(ckv, KV); // 8
    outv_kernel<<<NH * 8, 256>>>(kvb);                            // 9
    oproj_part<<<PBLOCKS, 128>>>(ow);                             // 10
    oproj_combine<<<(2 * H + 127) / 128, 128>>>(out);             // 11
}

// round 17
// speedup vs baseline: 1.0401x; 1.0401x over previous
#include <cuda_runtime.h>
#include <math.h>

#define H    5120
#define NH   128
#define QLR  1536
#define DR   64
#define KVLR 512
#define DV   128
#define DN   128
#define DQ   192
#define BMAX 2
#define KVMAX 2048

#define NSM     148
#define PBLOCKS (NSM * 12)        // persistent grid for oproj: 12 x 128 thr / SM
#define PWARPS  (PBLOCKS * 4)

// ---------------- scratch (device globals; no allocation allowed) ----------------
__device__ float g_qa[BMAX * QLR];
__device__ float g_q[BMAX * NH * DQ];
__device__ float g_qpe[BMAX * NH * DR];
__device__ float g_qabs2[2][BMAX * NH * KVLR];   // d-half partials
__device__ float g_kpe[BMAX * KVMAX * DR];
__device__ float g_scores[BMAX * NH * KVMAX];
__device__ float g_part[4][BMAX * NH * KVLR];
__device__ float g_outv[BMAX * NH * DV];
__device__ float g_opart0[H * 16];
__device__ float g_opart1[H * 16];

__device__ __forceinline__ float warp_sum(float v) {
    #pragma unroll
    for (int o = 16; o; o >>= 1) v += __shfl_xor_sync(0xFFFFFFFFu, v, o);
    return v;
}

// ---- packed fp32x2 helpers (sm_100+; SASS FFMA2 -> 2x fp32 MAC rate, bit-exact) ----
__device__ __forceinline__ unsigned long long pack2(float lo, float hi) {
    unsigned long long r;
    asm("mov.b64 %0, {%1, %2};" : "=l"(r) : "f"(lo), "f"(hi));
    return r;
}
__device__ __forceinline__ void unpack2(unsigned long long v, float& lo, float& hi) {
    asm("mov.b64 {%0, %1}, %2;" : "=f"(lo), "=f"(hi) : "l"(v));
}
__device__ __forceinline__ void ffma2(unsigned long long& d, unsigned long long a, unsigned long long b) {
    asm("fma.rn.f32x2 %0, %1, %2, %0;" : "+l"(d) : "l"(a), "l"(b));
}

// ---------------- RoPE on k_pe cache (5th launch; independent, done before scores) ----------------
#define LOG2_THETA 13.287712379549449f
__global__ void __launch_bounds__(256) rope_k_kernel(const float* __restrict__ kpe, int KV) {
    int idx = blockIdx.x * 256 + threadIdx.x;
    if (idx >= 2 * KV * 32) return;
    int i = idx & 31;
    int k = (idx >> 5) % KV;
    int b = idx / (KV * 32);
    float ifr = exp2f(-LOG2_THETA * (float)(2 * i) / 64.0f);
    float s, c; __sincosf((float)k * ifr, &s, &c);
    size_t base = ((size_t)b * KV + k) * DR + 2 * i;
    float x0 = kpe[base], x1 = kpe[base + 1];
    g_kpe[base]     = x0 * c - x1 * s;
    g_kpe[base + 1] = x0 * s + x1 * c;
}

// ---------------- q_a = hidden @ q_a_w^T (block per row) ----------------
__global__ void __launch_bounds__(128) qa_gemv(const float* __restrict__ hs, const float* __restrict__ w) {
    int row = blockIdx.x;
    int tid = threadIdx.x;  // 128
    const float4* wr = (const float4*)(w + (size_t)row * H);
    const float4* x0 = (const float4*)hs;
    const float4* x1 = (const float4*)(hs + H);
    float a0 = 0.f, a1 = 0.f;
    #pragma unroll 10
    for (int c = tid; c < H / 4; c += 128) {
        float4 wv = __ldcs(&wr[c]);
        float4 v0 = x0[c], v1 = x1[c];
        a0 += wv.x * v0.x + wv.y * v0.y + wv.z * v0.z + wv.w * v0.w;
        a1 += wv.x * v1.x + wv.y * v1.y + wv.z * v1.z + wv.w * v1.w;
    }
    a0 = warp_sum(a0); a1 = warp_sum(a1);
    __shared__ float r0[4], r1[4];
    int lane = tid & 31, wid = tid >> 5;
    if (!lane) { r0[wid] = a0; r1[wid] = a1; }
    __syncthreads();
    if (tid == 0) g_qa[row]       = r0[0] + r0[1] + r0[2] + r0[3];
    if (tid == 1) g_qa[QLR + row] = r1[0] + r1[1] + r1[2] + r1[3];
}

// ---------------- RMSNorm(q_a) in place ----------------
__global__ void __launch_bounds__(512) rmsnorm_k(const float* __restrict__ lnw) {
    int b = blockIdx.x, tid = threadIdx.x;
    float x[3]; float ss = 0.f;
    #pragma unroll
    for (int i = 0; i < 3; i++) { x[i] = g_qa[b * QLR + tid + i * 512]; ss += x[i] * x[i]; }
    __shared__ float red[512];
    red[tid] = ss; __syncthreads();
    for (int s = 256; s; s >>= 1) { if (tid < s) red[tid] += red[tid + s]; __syncthreads(); }
    float inv = rsqrtf(red[0] / (float)QLR + 1e-6f);
    #pragma unroll
    for (int i = 0; i < 3; i++)
        g_qa[b * QLR + tid + i * 512] = x[i] * inv * lnw[tid + i * 512];
}

// ---------------- q = q_a @ q_b_w^T (R6-best: 2 rows/warp, grid 3072x128) ----------------
__global__ void __launch_bounds__(128) qb_gemv(const float* __restrict__ w) {
    int wid  = threadIdx.x >> 5;
    int lane = threadIdx.x & 31;
    int r0 = blockIdx.x * 8 + wid * 2;           // rows r0, r0+1
    const float4* w0 = (const float4*)(w + (size_t)r0 * QLR);
    const float4* w1 = (const float4*)(w + (size_t)(r0 + 1) * QLR);
    const float4* x0 = (const float4*)g_qa;
    const float4* x1 = (const float4*)(g_qa + QLR);
    float a00 = 0.f, a01 = 0.f, a10 = 0.f, a11 = 0.f;
    #pragma unroll 6
    for (int c = lane; c < QLR / 4; c += 32) {
        float4 wa = __ldcs(&w0[c]);
        float4 wb = __ldcs(&w1[c]);
        float4 v0 = x0[c], v1 = x1[c];
        a00 += wa.x * v0.x + wa.y * v0.y + wa.z * v0.z + wa.w * v0.w;
        a01 += wa.x * v1.x + wa.y * v1.y + wa.z * v1.z + wa.w * v1.w;
        a10 += wb.x * v0.x + wb.y * v0.y + wb.z * v0.z + wb.w * v0.w;
        a11 += wb.x * v1.x + wb.y * v1.y + wb.z * v1.z + wb.w * v1.w;
    }
    a00 = warp_sum(a00); a01 = warp_sum(a01);
    a10 = warp_sum(a10); a11 = warp_sum(a11);
    if (!lane) {
        g_q[r0] = a00;           g_q[NH * DQ + r0] = a01;
        g_q[r0 + 1] = a10;       g_q[NH * DQ + r0 + 1] = a11;
    }
}

// ------- q_abs d-split + fused rope_q.  grid 256 = (head, d-half), 512 thr.  -- ncu slot -------
// block (h, dh) reduces d in [dh*64, dh*64+64) over all 512 c -> g_qabs2[dh]
__global__ void __launch_bounds__(512) qabs_kernel(const float* __restrict__ kvb, int KV) {
    int h = blockIdx.x >> 1, dh = blockIdx.x & 1;
    int c = threadIdx.x;       // 0..511
    __shared__ float qn[2][64];
    if (c < 128) {
        int b = c >> 6, d = c & 63;
        qn[b][d] = g_q[b * NH * DQ + h * DQ + dh * 64 + d];
    }
    // fused rope_q (once per head, in the dh==0 block), threads 256..319
    if (dh == 0 && c >= 256 && c < 320) {
        int b = (c - 256) >> 5, i = c & 31;
        float ifr = exp2f(-LOG2_THETA * (float)(2 * i) / 64.0f);
        float s, co; __sincosf((float)(KV - 1) * ifr, &s, &co);
        float x0 = g_q[b * NH * DQ + h * DQ + DN + 2 * i];
        float x1 = g_q[b * NH * DQ + h * DQ + DN + 2 * i + 1];
        g_qpe[(b * NH + h) * DR + 2 * i]     = x0 * co - x1 * s;
        g_qpe[(b * NH + h) * DR + 2 * i + 1] = x0 * s + x1 * co;
    }
    __syncthreads();
    const float* wp = kvb + (size_t)(h * 256 + dh * 64) * KVLR + c;
    float a0 = 0.f, a1 = 0.f;
    #pragma unroll 16
    for (int d = 0; d < 64; d++) {
        float w = __ldcs(&wp[(size_t)d * KVLR]);
        a0 += qn[0][d] * w;
        a1 += qn[1][d] * w;
    }
    g_qabs2[dh][h * KVLR + c] = a0;
    g_qabs2[dh][NH * KVLR + h * KVLR + c] = a1;
}

// ---------------- scores: 32-head x 128-k tiles; Qs = sum of two d-half partials ----------------
__global__ void __launch_bounds__(256) scores_kernel(const float* __restrict__ ckv, int KV) {
    __shared__ float Qs[32][66];
    __shared__ float KsT[64][130];
    int b = blockIdx.z, h0 = blockIdx.y * 32, k0 = blockIdx.x * 128;
    int tid = threadIdx.x, lane = tid & 31, wid = tid >> 5;
    unsigned long long acc[4][2] = {};
    for (int chunk = 0; chunk < 9; chunk++) {
        if (chunk < 8) {
            int c0 = chunk * 64;
            #pragma unroll
            for (int t = tid; t < 32 * 16; t += 256) {
                int r = t >> 4, c4 = t & 15;
                size_t ix = (size_t)((b * NH) + h0 + r) * KVLR + c0 + c4 * 4;
                float4 u = *(const float4*)&g_qabs2[0][ix];
                float4 w = *(const float4*)&g_qabs2[1][ix];
                Qs[r][c4*4+0] = u.x + w.x; Qs[r][c4*4+1] = u.y + w.y;
                Qs[r][c4*4+2] = u.z + w.z; Qs[r][c4*4+3] = u.w + w.w;
            }
            int c = tid & 63, kk = tid >> 6;
            #pragma unroll 8
            for (int kq = 0; kq < 32; kq++) {
                int k = kq * 4 + kk;
                KsT[c][k] = ckv[((size_t)b * KV + k0 + k) * KVLR + c0 + c];
            }
        } else {
            #pragma unroll
            for (int t = tid; t < 32 * 16; t += 256) {
                int r = t >> 4, c4 = t & 15;
                float4 v = *(const float4*)&g_qpe[((b * NH) + h0 + r) * DR + c4 * 4];
                Qs[r][c4*4+0] = v.x; Qs[r][c4*4+1] = v.y; Qs[r][c4*4+2] = v.z; Qs[r][c4*4+3] = v.w;
            }
            int c = tid & 63, kk = tid >> 6;
            #pragma unroll 8
            for (int kq = 0; kq < 32; kq++) {
                int k = kq * 4 + kk;
                KsT[c][k] = g_kpe[((size_t)b * KV + k0 + k) * DR + c];
            }
        }
        __syncthreads();
        #pragma unroll 8
        for (int cc = 0; cc < 64; cc++) {
            unsigned long long kA = *(const unsigned long long*)&KsT[cc][lane * 2];
            unsigned long long kB = *(const unsigned long long*)&KsT[cc][lane * 2 + 64];
            #pragma unroll
            for (int i = 0; i < 4; i++) {
                float q = Qs[wid + 8 * i][cc];
                unsigned long long qq = pack2(q, q);
                ffma2(acc[i][0], qq, kA);
                ffma2(acc[i][1], qq, kB);
            }
        }
        __syncthreads();
    }
    const float sc = rsqrtf((float)DQ);
    #pragma unroll
    for (int i = 0; i < 4; i++) {
        #pragma unroll
        for (int jj = 0; jj < 2; jj++) {
            float lo, hi; unpack2(acc[i][jj], lo, hi);
            float2 v = make_float2(lo * sc, hi * sc);
            *(float2*)&g_scores[(size_t)(b * NH + h0 + wid + 8 * i) * KV + k0 + lane * 2 + 64 * jj] = v;
        }
    }
}

// ---------------- softmax over k ----------------
__global__ void __launch_bounds__(256) softmax_kernel(int KV) {
    int bh = blockIdx.x;
    float* s = g_scores + (size_t)bh * KV;
    int tid = threadIdx.x;
    int n = KV >> 8;
    float v[8];
    float m = -1e30f;
    for (int i = 0; i < n; i++) { v[i] = s[tid + i * 256]; m = fmaxf(m, v[i]); }
    __shared__ float red[256];
    red[tid] = m; __syncthreads();
    for (int st = 128; st; st >>= 1) { if (tid < st) red[tid] = fmaxf(red[tid], red[tid + st]); __syncthreads(); }
    m = red[0]; __syncthreads();
    float sum = 0.f;
    for (int i = 0; i < n; i++) { v[i] = __expf(v[i] - m); sum += v[i]; }
    red[tid] = sum; __syncthreads();
    for (int st = 128; st; st >>= 1) { if (tid < st) red[tid] += red[tid + st]; __syncthreads(); }
    float inv = 1.f / red[0];
    for (int i = 0; i < n; i++) s[tid + i * 256] = v[i] * inv;
}

// ---------------- partial attn·c_kv (split-K = 4), FFMA2-packed ----------------
__global__ void __launch_bounds__(256) actv_kernel(const float* __restrict__ ckv, int KV) {
    __shared__ float As[32][68];
    __shared__ float Bs[64][128];
    int c0 = blockIdx.x * 128, h0 = blockIdx.y * 32;
    int b = blockIdx.z >> 2, sp = blockIdx.z & 3;
    int kbeg = sp * (KV / 4);
    int tid = threadIdx.x, lane = tid & 31, wid = tid >> 5;
    unsigned long long acc[4][2] = {};
    for (int kc0 = kbeg; kc0 < kbeg + KV / 4; kc0 += 64) {
        #pragma unroll
        for (int t = tid; t < 32 * 16; t += 256) {
            int r = t >> 4, c4 = t & 15;
            float4 v = *(const float4*)&g_scores[(size_t)(b * NH + h0 + r) * KV + kc0 + c4 * 4];
            *(float4*)&As[r][c4 * 4] = v;
        }
        #pragma unroll
        for (int t = tid; t < 64 * 32; t += 256) {
            int r = t >> 5, c4 = t & 31;
            *(float4*)&Bs[r][c4 * 4] =
                *(const float4*)&ckv[((size_t)b * KV + kc0 + r) * KVLR + c0 + c4 * 4];
        }
        __syncthreads();
        #pragma unroll 8
        for (int kc = 0; kc < 64; kc++) {
            unsigned long long b0 = *(const unsigned long long*)&Bs[kc][lane * 4];
            unsigned long long b1 = *(const unsigned long long*)&Bs[kc][lane * 4 + 2];
            #pragma unroll
            for (int i = 0; i < 4; i++) {
                float a = As[wid + 8 * i][kc];
                unsigned long long aa = pack2(a, a);
                ffma2(acc[i][0], aa, b0);
                ffma2(acc[i][1], aa, b1);
            }
        }
        __syncthreads();
    }
    #pragma unroll
    for (int i = 0; i < 4; i++) {
        float x0, x1, x2, x3;
        unpack2(acc[i][0], x0, x1);
        unpack2(acc[i][1], x2, x3);
        float4 v = make_float4(x0, x1, x2, x3);
        *(float4*)&g_part[sp][(size_t)(b * NH + h0 + wid + 8 * i) * KVLR + c0 + lane * 4] = v;
    }
}

// ---------------- out_v: grid 1024 = (h, dv-eighth), warp = 2 dv rows ----------------
__global__ void __launch_bounds__(256) outv_kernel(const float* __restrict__ kvb) {
    int h = blockIdx.x >> 3, dvE = blockIdx.x & 7;
    __shared__ float as[2][KVLR];
    int tid = threadIdx.x;
    for (int t = tid; t < 2 * KVLR; t += 256) {
        int b = t >> 9, c = t & 511;
        float v = 0.f;
        #pragma unroll
        for (int sp = 0; sp < 4; sp++) v += g_part[sp][(size_t)(b * NH + h) * KVLR + c];
        as[b][c] = v;
    }
    __syncthreads();
    int lane = tid & 31, wid = tid >> 5;
    int dv0 = dvE * 16 + wid * 2;
    const float4* wp0 = (const float4*)(kvb + (size_t)(h * 256 + 128 + dv0 + 0) * KVLR);
    const float4* wp1 = (const float4*)(kvb + (size_t)(h * 256 + 128 + dv0 + 1) * KVLR);
    float a0[2] = {0.f, 0.f};
    float a1[2] = {0.f, 0.f};
    #pragma unroll
    for (int c4 = lane; c4 < KVLR / 4; c4 += 32) {
        float4 w0 = __ldcs(&wp0[c4]);
        float4 w1 = __ldcs(&wp1[c4]);
        float4 v0 = *(const float4*)&as[0][c4 * 4];
        float4 v1 = *(const float4*)&as[1][c4 * 4];
        a0[0] += w0.x*v0.x + w0.y*v0.y + w0.z*v0.z + w0.w*v0.w;
        a1[0] += w0.x*v1.x + w0.y*v1.y + w0.z*v1.z + w0.w*v1.w;
        a0[1] += w1.x*v0.x + w1.y*v0.y + w1.z*v0.z + w1.w*v0.w;
        a1[1] += w1.x*v1.x + w1.y*v1.y + w1.z*v1.z + w1.w*v1.w;
    }
    #pragma unroll
    for (int r = 0; r < 2; r++) {
        a0[r] = warp_sum(a0[r]);
        a1[r] = warp_sum(a1[r]);
    }
    if (!lane) {
        #pragma unroll
        for (int r = 0; r < 2; r++) {
            g_outv[h * DV + dv0 + r] = a0[r];
            g_outv[NH * DV + h * DV + dv0 + r] = a1[r];
        }
    }
}

// ------- o_proj stage 1: persistent warp-tasks (row, sixteenth of K) -------
__global__ void __launch_bounds__(128, 12) oproj_part(const float* __restrict__ ow) {
    int lane = threadIdx.x & 31;
    int wgid = (blockIdx.x * 4) + (threadIdx.x >> 5);
    const int NT = H * 16;
    const float4* x0 = (const float4*)g_outv;
    const float4* x1 = (const float4*)(g_outv + NH * DV);
    for (int t = wgid; t < NT; t += PWARPS) {
        int row = t >> 4, six = t & 15;
        int cbase = six * 256;
        const float4* wr = (const float4*)(ow + (size_t)row * (NH * DV)) + cbase;
        const float4* p0 = x0 + cbase;
        const float4* p1 = x1 + cbase;
        float a0 = 0.f, a1 = 0.f;
        #pragma unroll
        for (int c = lane; c < 256; c += 32) {
            float4 wv = __ldcs(&wr[c]);
            float4 v0 = p0[c], v1 = p1[c];
            a0 += wv.x * v0.x + wv.y * v0.y + wv.z * v0.z + wv.w * v0.w;
            a1 += wv.x * v1.x + wv.y * v1.y + wv.z * v1.z + wv.w * v1.w;
        }
        a0 = warp_sum(a0); a1 = warp_sum(a1);
        if (!lane) { g_opart0[t] = a0; g_opart1[t] = a1; }
    }
}

// ------- o_proj stage 2: combine 16 partials per output -------
__global__ void __launch_bounds__(128) oproj_combine(float* __restrict__ out) {
    int idx = blockIdx.x * 128 + threadIdx.x;
    if (idx >= 2 * H) return;
    int b = idx >= H;
    int row = b ? (idx - H) : idx;
    const float4* p = (const float4*)((b ? g_opart1 : g_opart0) + row * 16);
    float s = 0.f;
    #pragma unroll
    for (int q = 0; q < 4; q++) {
        float4 v = p[q];
        s += v.x + v.y + v.z + v.w;
    }
    out[idx] = s;
}

// ---------------- launch ----------------
extern "C" void kernel_launch(void* const* d_in, const int* in_sizes, int n_in,
                              void* d_out, int out_size) {
    const float* hidden = (const float*)d_in[0];
    const float* ckv    = (const float*)d_in[1];
    const float* kpe    = (const float*)d_in[2];
    const float* qaw    = (const float*)d_in[3];
    const float* lnw    = (const float*)d_in[4];
    const float* qbw    = (const float*)d_in[5];
    const float* kvb    = (const float*)d_in[6];
    const float* ow     = (const float*)d_in[7];
    float* out = (float*)d_out;

    int B  = in_sizes[0] / H;          // 2
    int KV = in_sizes[2] / (B * DR);   // 2048

    qa_gemv<<<QLR, 128>>>(hidden, qaw);                           // 1
    rmsnorm_k<<<B, 512>>>(lnw);                                   // 2
    qb_gemv<<<(NH * DQ) / 8, 128>>>(qbw);                         // 3
    qabs_kernel<<<NH * 2, 512>>>(kvb, KV);                        // 4  <- ncu slot
    rope_k_kernel<<<(B * KV * 32 + 255) / 256, 256>>>(kpe, KV);   // 5 (indep; done before scores)
    scores_kernel<<<dim3(KV / 128, NH / 32, B), 256>>>(ckv, KV);  // 6
    softmax_kernel<<<B * NH, 256>>>(KV);                          // 7
    actv_kernel<<<dim3(KVLR / 128, NH / 32, B * 4), 256>>>(ckv, KV); // 8
    outv_kernel<<<NH * 8, 256>>>(kvb);                            // 9
    oproj_part<<<PBLOCKS, 128>>>(ow);                             // 10
    oproj_combine<<<(2 * H + 127) / 128, 128>>>(out);             // 11
}